// round 14
// baseline (speedup 1.0000x reference)
#include <cuda_runtime.h>
#include <cuda_fp16.h>
#include <cstdint>

#define BATCH 4096
#define NPAIR (BATCH / 2)

// ---------------- device-global staging (written by pre-kernel) ----------------
// gWimg: fp16 B ldmatrix image, [chunk 8][nblk 8][kblk 8][tile 256B]
//   tile = 8 n-slots x 16 k fp16, slot nr at ((nr*32 + kh*16) ^ ((nr&4)?16:0)) + (k&7)*2
//   N-permutation: chunk=n>>6, cc=n&63, nhalf=cc>>5, w32=cc&31,
//     j=w32>>3, g=(w32>>1)&3, r=w32&1 ; nblk = nhalf*4 + g ; slot = 2j + r
__device__ __align__(1024) unsigned char gWimg[131072];
// gT[half][f][h] = sum_c Wlin[f][c] * Watt[(half*512 + c)*8 + h]
__device__ __align__(16) float gT[2][128][8];

// ---------------- PTX helpers ----------------
__device__ __forceinline__ uint32_t smem_u32(const void* p) {
    uint32_t a;
    asm("{ .reg .u64 t; cvta.to.shared.u64 t, %1; cvt.u32.u64 %0, t; }" : "=r"(a) : "l"(p));
    return a;
}
__device__ __forceinline__ void cp_async16(uint32_t saddr, const void* g) {
    asm volatile("cp.async.cg.shared.global [%0], [%1], 16;" :: "r"(saddr), "l"(g));
}
__device__ __forceinline__ void cp_commit() { asm volatile("cp.async.commit_group;"); }
template<int N> __device__ __forceinline__ void cp_wait() {
    asm volatile("cp.async.wait_group %0;" :: "n"(N));
}

#define LDSM_X4(d, a)                                                             \
    asm volatile("ldmatrix.sync.aligned.m8n8.x4.shared.b16 {%0,%1,%2,%3}, [%4];"  \
        : "=r"((d)[0]), "=r"((d)[1]), "=r"((d)[2]), "=r"((d)[3]) : "r"(a))

__device__ __forceinline__ void mmaf16(float* c, const uint32_t* a,
                                       uint32_t b0, uint32_t b1) {
    asm volatile("mma.sync.aligned.m16n8k16.row.col.f32.f16.f16.f32 "
        "{%0,%1,%2,%3}, {%4,%5,%6,%7}, {%8,%9}, {%0,%1,%2,%3};"
        : "+f"(c[0]), "+f"(c[1]), "+f"(c[2]), "+f"(c[3])
        : "r"(a[0]), "r"(a[1]), "r"(a[2]), "r"(a[3]), "r"(b0), "r"(b1));
}

__device__ __forceinline__ uint32_t pkh2(float a, float b) {
    __half2 t = __floats2half2_rn(a, b);
    return *reinterpret_cast<uint32_t*>(&t);
}

// ---------------- fused pre-kernel (unchanged) ----------------
__global__ void k_prep(const float* __restrict__ Wlin, const float* __restrict__ Watt) {
    int blk = blockIdx.x;
    if (blk < 32) {
        int t = blk * 256 + threadIdx.x;      // 0..8191
        int n = t & 511, ko = t >> 9;          // ko: 16 k-octs
        float v[8];
        #pragma unroll
        for (int j = 0; j < 8; ++j)
            v[j] = Wlin[(size_t)(ko * 8 + j) * 512 + n];
        int chunk = n >> 6, cc = n & 63, nhalf = cc >> 5, w32 = cc & 31;
        int jj = w32 >> 3, g = (w32 >> 1) & 3, r = w32 & 1;
        int nblk = chunk * 8 + nhalf * 4 + g;
        int nr = jj * 2 + r;
        int kblk = ko >> 1, kh = ko & 1;
        uint32_t off = (uint32_t)nblk * 2048u + (uint32_t)kblk * 256u
                     + (((uint32_t)nr * 32u + (uint32_t)kh * 16u) ^ ((nr & 4) ? 16u : 0u));
        *(uint4*)(&gWimg[off]) = make_uint4(pkh2(v[0], v[1]), pkh2(v[2], v[3]),
                                            pkh2(v[4], v[5]), pkh2(v[6], v[7]));
    } else {
        int t = (blk - 32) * 256 + threadIdx.x;   // 0..16383
        int o = t >> 3, sub = t & 7;               // 2048 outputs, 8 threads each
        int half = o >> 10, f = (o >> 3) & 127, h = o & 7;
        const float* wl = Wlin + (size_t)f * 512;
        const float* wa = Watt + (size_t)half * 512 * 8 + h;
        float acc = 0.f;
        int c0 = sub * 64;
        #pragma unroll 8
        for (int c = c0; c < c0 + 64; ++c)
            acc += wl[c] * wa[(size_t)c * 8];
        #pragma unroll
        for (int off = 4; off > 0; off >>= 1)
            acc += __shfl_xor_sync(0xffffffffu, acc, off);
        if (sub == 0) gT[half][f][h] = acc;
    }
}

// ---------------- main kernel: 256 threads, 2 batches, 2 CTAs/SM ----------------
// Warp tiling: mslice = w>>1 (m=32 rows of the 128), nhalf = w&1 (n=32/chunk)
// SMEM (bytes): A image [mblk8][kblk8][512B] @0 (32KB)
//               B double buffer 2 x 16KB @32768 (x 1-batch stage 32KB aliased)
//               T1 (4KB) @65536 ; SS[2][8] @69632 ; ATT[2][8][64] @69696
#define SM_A   0
#define SM_B   32768
#define SM_T1  65536
#define SM_SS  69632
#define SM_ATT 69696
#define SMEM_BYTES 73792

__global__ void __launch_bounds__(256, 2)
agg_main(const float* __restrict__ x, const int* __restrict__ mask,
         float* __restrict__ out)
{
    extern __shared__ unsigned char sm[];
    const int t = threadIdx.x, w = t >> 5, lane = t & 31;
    const int b0 = blockIdx.x * 2;
    const uint32_t sb = smem_u32(sm);
    float* stage = (float*)(sm + SM_B);            // aliased on B buf0+buf1
    float* attb  = (float*)(sm + SM_ATT);
    float* sS    = (float*)(sm + SM_SS);
    const float* sT1 = (float*)(sm + SM_T1);
    const float* gT0 = &gT[0][0][0];

    // ---- T1 -> smem (4KB) ----
    cp_async16(sb + SM_T1 + t * 16, (const char*)&gT[1][0][0] + t * 16);
    cp_commit();

    // ---- two x passes: stage batch p, convert to A image, raw logits ----
    #pragma unroll
    for (int ps = 0; ps < 2; ++ps) {
        const float* xp = x + (size_t)(b0 + ps) * 8192;
        #pragma unroll
        for (int i = 0; i < 8; ++i) {
            int idx = t + i * 256;
            cp_async16(sb + SM_B + idx * 16, (const char*)xp + idx * 16);
        }
        cp_commit();
        cp_wait<0>();
        __syncthreads();

        // convert rows ps*64 .. ps*64+63 -> A image
        #pragma unroll
        for (int i = 0; i < 4; ++i) {
            int idx = t + i * 256;
            int ml = idx >> 4, k0 = (idx & 15) * 8;
            float4 v0 = *(float4*)(stage + ml * 128 + k0);
            float4 v1 = *(float4*)(stage + ml * 128 + k0 + 4);
            int m = ps * 64 + ml;
            int mblk = m >> 4, rr = m & 15, kblk = k0 >> 4, kh = (k0 >> 3) & 1;
            uint32_t off = (uint32_t)mblk * 4096u + (uint32_t)kblk * 512u
                         + (((uint32_t)rr * 32u + (uint32_t)kh * 16u) ^ ((rr & 4) ? 16u : 0u));
            *(uint4*)(sm + SM_A + off) = make_uint4(pkh2(v0.x, v0.y), pkh2(v0.z, v0.w),
                                                    pkh2(v1.x, v1.y), pkh2(v1.z, v1.w));
        }

        // raw logits dot -> attb (finalized later); x via LDS broadcast
        #pragma unroll
        for (int j = 0; j < 2; ++j) {
            int idx2 = t + j * 256;
            int r = idx2 >> 3, h = idx2 & 7;
            const float* xr = stage + r * 128;
            float acc = 0.f;
            #pragma unroll 4
            for (int k = 0; k < 128; k += 4) {
                float4 xv = *(float4*)(xr + k);
                acc += xv.x * sT1[(k + 0) * 8 + h];
                acc += xv.y * sT1[(k + 1) * 8 + h];
                acc += xv.z * sT1[(k + 2) * 8 + h];
                acc += xv.w * sT1[(k + 3) * 8 + h];
            }
            attb[(ps * 8 + h) * 64 + r] = acc;
        }
        float srcv = 0.f;
        if (t < 8) {        // src term: row 0 vs T0 (8 threads -> __ldg)
            const float* xr = stage;
            #pragma unroll 4
            for (int k = 0; k < 128; k += 4) {
                float4 xv = *(float4*)(xr + k);
                srcv += xv.x * __ldg(gT0 + (k + 0) * 8 + t);
                srcv += xv.y * __ldg(gT0 + (k + 1) * 8 + t);
                srcv += xv.z * __ldg(gT0 + (k + 2) * 8 + t);
                srcv += xv.w * __ldg(gT0 + (k + 3) * 8 + t);
            }
        }
        __syncthreads();    // stage fully read; A-image + raw attb visible
        if (t < 8) sS[ps * 8 + t] = srcv;
    }

    // ---- B chunk 0 -> buf0 (stage dead) ----
    #pragma unroll
    for (int i = 0; i < 4; ++i) {
        int u = t + i * 256;
        cp_async16(sb + SM_B + u * 16, &gWimg[u * 16]);
    }
    cp_commit();

    // ---- hoist A fragments (chunk-invariant): m=32/warp -> 64 regs ----
    const int mslice = w >> 1, nhalf = w & 1;
    const int ja = lane >> 3, ra = lane & 7;
    const int ml  = (ja & 1) * 8 + ra, kha = ja >> 1;
    const uint32_t arow = (((uint32_t)ml * 32u + (uint32_t)kha * 16u) ^ ((ml & 4) ? 16u : 0u));
    uint32_t af[2][8][4];
    #pragma unroll
    for (int mb = 0; mb < 2; ++mb) {
        const uint32_t aad = sb + SM_A + (uint32_t)(mslice * 2 + mb) * 4096u + arow;
        #pragma unroll
        for (int kblk = 0; kblk < 8; ++kblk)
            LDSM_X4(af[mb][kblk], aad + (uint32_t)kblk * 512u);
    }
    __syncthreads();    // sS visible

    // ---- finalize logits: leaky(sS + raw dot) ----
    #pragma unroll
    for (int i = 0; i < 4; ++i) {
        int idx = t + i * 256;              // 0..1023
        int ps = idx >> 9, r = (idx >> 3) & 63, h = idx & 7;
        float v = sS[ps * 8 + h] + attb[(ps * 8 + h) * 64 + r];
        v = (v >= 0.f) ? v : 0.2f * v;
        attb[(ps * 8 + h) * 64 + r] = v;
    }
    __syncthreads();

    // ---- softmax: warp w -> head w for both batches ----
    #pragma unroll
    for (int ps = 0; ps < 2; ++ps) {
        int m0 = mask[(b0 + ps) * 64 + lane];
        int m1 = mask[(b0 + ps) * 64 + lane + 32];
        float v0 = attb[(ps * 8 + w) * 64 + lane]      + (m0 == 0 ? -1e9f : 0.f);
        float v1 = attb[(ps * 8 + w) * 64 + lane + 32] + (m1 == 0 ? -1e9f : 0.f);
        float mx = fmaxf(v0, v1);
        #pragma unroll
        for (int o = 16; o > 0; o >>= 1) mx = fmaxf(mx, __shfl_xor_sync(0xffffffffu, mx, o));
        float e0 = __expf(v0 - mx), e1 = __expf(v1 - mx);
        float sum = e0 + e1;
        #pragma unroll
        for (int o = 16; o > 0; o >>= 1) sum += __shfl_xor_sync(0xffffffffu, sum, o);
        float inv = 1.f / sum;
        attb[(ps * 8 + w) * 64 + lane]      = e0 * inv;
        attb[(ps * 8 + w) * 64 + lane + 32] = e1 * inv;
    }

    // ---- B addressing + epilogue lane mapping ----
    const int nbo = (ja >> 1), khb = ja & 1;
    const uint32_t brow = (((uint32_t)ra * 32u + (uint32_t)khb * 16u) ^ ((ra & 4) ? 16u : 0u));
    const int er = lane >> 2, jc = lane & 3;
    const int batch = mslice >> 1;
    const int nr0 = (mslice & 1) * 32 + er;         // rows nr0, +8, +16, +24 (same batch)
    float* obase = out + ((size_t)(b0 + batch) * 64 + nr0) * 512 + nhalf * 32 + jc * 8;
    const float* awb = attb + (size_t)batch * 8 * 64;

    // ---- mainloop: 8 chunks (chunk == head), double-buffered B ----
    for (int c = 0; c < 8; ++c) {
        cp_wait<0>();          // chunk c arrived
        __syncthreads();       // visibility + prior-chunk consumers done
        if (c < 7) {
            uint32_t dst = sb + SM_B + (uint32_t)((c + 1) & 1) * 16384u;
            #pragma unroll
            for (int i = 0; i < 4; ++i) {
                int u = t + i * 256;
                cp_async16(dst + u * 16, &gWimg[(c + 1) * 16384 + u * 16]);
            }
            cp_commit();
        }

        const uint32_t bbase = sb + SM_B + (uint32_t)(c & 1) * 16384u;
        float acc[32];
        #pragma unroll
        for (int i = 0; i < 32; ++i) acc[i] = 0.f;

        // depth-1 pipelined B stream: flat iter i = kblk*2 + ng; 4 MMAs/LDSM
        uint32_t bh[2][4];
        {
            uint32_t bad = bbase + (uint32_t)(nhalf * 4 + nbo) * 2048u + brow;
            LDSM_X4(bh[0], bad);
        }
        #pragma unroll
        for (int i = 0; i < 16; ++i) {
            const int cur = i & 1, nxt = cur ^ 1;
            if (i < 15) {
                int kn = i + 1;
                uint32_t bad = bbase
                    + (uint32_t)(nhalf * 4 + (kn & 1) * 2 + nbo) * 2048u
                    + (uint32_t)(kn >> 1) * 256u + brow;
                LDSM_X4(bh[nxt], bad);
            }
            const int kblk = i >> 1, go = (i & 1) * 8;
            mmaf16(acc + go + 0,       af[0][kblk], bh[cur][0], bh[cur][1]);
            mmaf16(acc + go + 4,       af[0][kblk], bh[cur][2], bh[cur][3]);
            mmaf16(acc + 16 + go + 0,  af[1][kblk], bh[cur][0], bh[cur][1]);
            mmaf16(acc + 16 + go + 4,  af[1][kblk], bh[cur][2], bh[cur][3]);
        }

        // ---- epilogue: 4 rows x 8 contiguous floats per thread ----
        float sc0 = awb[c * 64 + nr0];
        float sc1 = awb[c * 64 + nr0 + 8];
        float sc2 = awb[c * 64 + nr0 + 16];
        float sc3 = awb[c * 64 + nr0 + 24];
        float* o = obase + c * 64;
        // row nr0      (mb0, even): acc{0,1,4,5} | acc{8,9,12,13}
        *(float4*)(o) = make_float4(
            fmaxf(acc[0]  * sc0, 0.f), fmaxf(acc[1]  * sc0, 0.f),
            fmaxf(acc[4]  * sc0, 0.f), fmaxf(acc[5]  * sc0, 0.f));
        *(float4*)(o + 4) = make_float4(
            fmaxf(acc[8]  * sc0, 0.f), fmaxf(acc[9]  * sc0, 0.f),
            fmaxf(acc[12] * sc0, 0.f), fmaxf(acc[13] * sc0, 0.f));
        // row nr0 + 8  (mb0, odd)
        *(float4*)(o + 8 * 512) = make_float4(
            fmaxf(acc[2]  * sc1, 0.f), fmaxf(acc[3]  * sc1, 0.f),
            fmaxf(acc[6]  * sc1, 0.f), fmaxf(acc[7]  * sc1, 0.f));
        *(float4*)(o + 8 * 512 + 4) = make_float4(
            fmaxf(acc[10] * sc1, 0.f), fmaxf(acc[11] * sc1, 0.f),
            fmaxf(acc[14] * sc1, 0.f), fmaxf(acc[15] * sc1, 0.f));
        // row nr0 + 16 (mb1, even)
        *(float4*)(o + 16 * 512) = make_float4(
            fmaxf(acc[16] * sc2, 0.f), fmaxf(acc[17] * sc2, 0.f),
            fmaxf(acc[20] * sc2, 0.f), fmaxf(acc[21] * sc2, 0.f));
        *(float4*)(o + 16 * 512 + 4) = make_float4(
            fmaxf(acc[24] * sc2, 0.f), fmaxf(acc[25] * sc2, 0.f),
            fmaxf(acc[28] * sc2, 0.f), fmaxf(acc[29] * sc2, 0.f));
        // row nr0 + 24 (mb1, odd)
        *(float4*)(o + 24 * 512) = make_float4(
            fmaxf(acc[18] * sc3, 0.f), fmaxf(acc[19] * sc3, 0.f),
            fmaxf(acc[22] * sc3, 0.f), fmaxf(acc[23] * sc3, 0.f));
        *(float4*)(o + 24 * 512 + 4) = make_float4(
            fmaxf(acc[26] * sc3, 0.f), fmaxf(acc[27] * sc3, 0.f),
            fmaxf(acc[30] * sc3, 0.f), fmaxf(acc[31] * sc3, 0.f));
    }
}

// ---------------- launch ----------------
extern "C" void kernel_launch(void* const* d_in, const int* in_sizes, int n_in,
                              void* d_out, int out_size)
{
    const float* x    = (const float*)d_in[0];
    const float* Wlin = (const float*)d_in[1];
    const float* Watt = (const float*)d_in[2];
    const int*   mk   = (const int*)d_in[3];
    float*       out  = (float*)d_out;

    k_prep<<<96, 256>>>(Wlin, Watt);

    cudaFuncSetAttribute(agg_main, cudaFuncAttributeMaxDynamicSharedMemorySize, SMEM_BYTES);
    agg_main<<<NPAIR, 256, SMEM_BYTES>>>(x, mk, out);
}

// round 15
// speedup vs baseline: 1.1486x; 1.1486x over previous
#include <cuda_runtime.h>
#include <cuda_fp16.h>
#include <cstdint>

#define BATCH 4096

// ---------------- device-global staging (written by pre-kernel) ----------------
// gWimg: fp16 B ldmatrix image, [chunk 8][nblk 8][kblk 8][tile 256B]
//   tile = 8 n-slots x 16 k fp16, slot nr at ((nr*32 + kh*16) ^ ((nr&4)?16:0)) + (k&7)*2
//   N-permutation: chunk=n>>6, cc=n&63, nhalf=cc>>5, w32=cc&31,
//     j=w32>>3, g=(w32>>1)&3, r=w32&1 ; nblk = nhalf*4 + g ; slot = 2j + r
__device__ __align__(1024) unsigned char gWimg[131072];
// gTt[half][h][f] = sum_c Wlin[f][c] * Watt[(half*512 + c)*8 + h]   (TRANSPOSED)
__device__ __align__(16) float gTt[2][8][128];

// ---------------- PTX helpers ----------------
__device__ __forceinline__ uint32_t smem_u32(const void* p) {
    uint32_t a;
    asm("{ .reg .u64 t; cvta.to.shared.u64 t, %1; cvt.u32.u64 %0, t; }" : "=r"(a) : "l"(p));
    return a;
}
__device__ __forceinline__ void cp_async16(uint32_t saddr, const void* g) {
    asm volatile("cp.async.cg.shared.global [%0], [%1], 16;" :: "r"(saddr), "l"(g));
}
__device__ __forceinline__ void cp_commit() { asm volatile("cp.async.commit_group;"); }
template<int N> __device__ __forceinline__ void cp_wait() {
    asm volatile("cp.async.wait_group %0;" :: "n"(N));
}

#define LDSM_X4(d, a)                                                             \
    asm volatile("ldmatrix.sync.aligned.m8n8.x4.shared.b16 {%0,%1,%2,%3}, [%4];"  \
        : "=r"((d)[0]), "=r"((d)[1]), "=r"((d)[2]), "=r"((d)[3]) : "r"(a))

__device__ __forceinline__ void mmaf16(float* c, const uint32_t* a,
                                       uint32_t b0, uint32_t b1) {
    asm volatile("mma.sync.aligned.m16n8k16.row.col.f32.f16.f16.f32 "
        "{%0,%1,%2,%3}, {%4,%5,%6,%7}, {%8,%9}, {%0,%1,%2,%3};"
        : "+f"(c[0]), "+f"(c[1]), "+f"(c[2]), "+f"(c[3])
        : "r"(a[0]), "r"(a[1]), "r"(a[2]), "r"(a[3]), "r"(b0), "r"(b1));
}

__device__ __forceinline__ uint32_t pkh2(float a, float b) {
    __half2 t = __floats2half2_rn(a, b);
    return *reinterpret_cast<uint32_t*>(&t);
}

// ---------------- fused pre-kernel ----------------
__global__ void k_prep(const float* __restrict__ Wlin, const float* __restrict__ Watt) {
    int blk = blockIdx.x;
    if (blk < 32) {
        int t = blk * 256 + threadIdx.x;      // 0..8191
        int n = t & 511, ko = t >> 9;          // ko: 16 k-octs
        float v[8];
        #pragma unroll
        for (int j = 0; j < 8; ++j)
            v[j] = Wlin[(size_t)(ko * 8 + j) * 512 + n];
        int chunk = n >> 6, cc = n & 63, nhalf = cc >> 5, w32 = cc & 31;
        int jj = w32 >> 3, g = (w32 >> 1) & 3, r = w32 & 1;
        int nblk = chunk * 8 + nhalf * 4 + g;
        int nr = jj * 2 + r;
        int kblk = ko >> 1, kh = ko & 1;
        uint32_t off = (uint32_t)nblk * 2048u + (uint32_t)kblk * 256u
                     + (((uint32_t)nr * 32u + (uint32_t)kh * 16u) ^ ((nr & 4) ? 16u : 0u));
        *(uint4*)(&gWimg[off]) = make_uint4(pkh2(v[0], v[1]), pkh2(v[2], v[3]),
                                            pkh2(v[4], v[5]), pkh2(v[6], v[7]));
    } else {
        int t = (blk - 32) * 256 + threadIdx.x;   // 0..16383
        int o = t >> 3, sub = t & 7;               // 2048 outputs, 8 threads each
        int half = o >> 10, f = (o >> 3) & 127, h = o & 7;
        const float* wl = Wlin + (size_t)f * 512;
        const float* wa = Watt + (size_t)half * 512 * 8 + h;
        float acc = 0.f;
        int c0 = sub * 64;
        #pragma unroll 8
        for (int c = c0; c < c0 + 64; ++c)
            acc += wl[c] * wa[(size_t)c * 8];
        #pragma unroll
        for (int off = 4; off > 0; off >>= 1)
            acc += __shfl_xor_sync(0xffffffffu, acc, off);
        if (sub == 0) gTt[half][h][f] = acc;       // transposed store
    }
}

// ---------------- main kernel: 256 threads, 1 batch, 4 CTAs/SM ----------------
// Warp tiling (R13): mblk = w>>1 (m=16), nhalf = w&1 (n=32)
// SMEM (bytes): A image [mblk4][kblk8][512B] @0 (16KB)
//               B double buffer 2 x 16KB @16384 (x stage, XOR-swizzled, aliased)
//               T1t [8][132] fp32 @49152 (4224B) ; SS[8] @53376 ; ATT[8][64] @53408
//               total 55456 -> 4 CTAs/SM (221.8KB)
#define SM_A   0
#define SM_B   16384
#define SM_T1  49152
#define SM_SS  53376
#define SM_ATT 53408
#define SMEM_BYTES 55456

__global__ void __launch_bounds__(256, 4)
agg_main(const float* __restrict__ x, const int* __restrict__ mask,
         float* __restrict__ out)
{
    extern __shared__ unsigned char sm[];
    const int t = threadIdx.x, w = t >> 5, lane = t & 31;
    const int b = blockIdx.x;
    const uint32_t sb = smem_u32(sm);
    const unsigned char* stageB = sm + SM_B;       // swizzled x stage (aliased on B)
    float* attb  = (float*)(sm + SM_ATT);
    float* sS    = (float*)(sm + SM_SS);
    const float* sT1t = (float*)(sm + SM_T1);      // [8][132]
    const float* gT0  = &gTt[0][0][0];

    // ---- G0: x (32KB, row-swizzled) + T1t (4KB, rows padded to 132 floats) ----
    const float* xp = x + (size_t)b * 8192;
    #pragma unroll
    for (int i = 0; i < 8; ++i) {
        int idx = t + i * 256;                     // 16B chunk id, 0..2047
        int row = idx >> 5, cin = idx & 31;
        uint32_t dst = sb + SM_B + (uint32_t)row * 512u
                     + (((uint32_t)cin * 16u) ^ ((uint32_t)(row & 3) * 32u));
        cp_async16(dst, (const char*)xp + idx * 16);
    }
    {
        int h = t >> 5, c16 = t & 31;
        cp_async16(sb + SM_T1 + (uint32_t)h * 528u + (uint32_t)c16 * 16u,
                   (const char*)&gTt[1][0][0] + t * 16);
    }
    cp_commit();
    cp_wait<0>();
    __syncthreads();

    // ---- convert x -> fp16 A tile image (swizzled stage reads) ----
    #pragma unroll
    for (int i = 0; i < 4; ++i) {
        int idx = t + i * 256;
        int m = idx >> 4, k0 = (idx & 15) * 8;      // m 0..63
        const unsigned char* rowp = stageB + m * 512;
        uint32_t cr = (uint32_t)(m & 3) * 32u;
        float4 v0 = *(const float4*)(rowp + (((uint32_t)k0 * 4u) ^ cr));
        float4 v1 = *(const float4*)(rowp + (((uint32_t)(k0 + 4) * 4u) ^ cr));
        int mblk = m >> 4, rr = m & 15, kblk = k0 >> 4, kh = (k0 >> 3) & 1;
        uint32_t off = (uint32_t)mblk * 4096u + (uint32_t)kblk * 512u
                     + (((uint32_t)rr * 32u + (uint32_t)kh * 16u) ^ ((rr & 4) ? 16u : 0u));
        *(uint4*)(sm + SM_A + off) = make_uint4(pkh2(v0.x, v0.y), pkh2(v0.z, v0.w),
                                                pkh2(v1.x, v1.y), pkh2(v1.z, v1.w));
    }

    // ---- attention logits: 512 (r,h) tasks; x swizzled (1 wf), T1t vec (1 wf) ----
    float dotv[2]; int rr2[2], hh2[2];
    #pragma unroll
    for (int j = 0; j < 2; ++j) {
        int idx2 = t + j * 256;
        int r = idx2 >> 3, h = idx2 & 7;
        const unsigned char* xrb = stageB + r * 512;
        uint32_t cr = (uint32_t)(r & 3) * 32u;
        const float* tr = sT1t + h * 132;
        float acc = 0.f;
        #pragma unroll 4
        for (int k = 0; k < 128; k += 4) {
            float4 xv = *(const float4*)(xrb + (((uint32_t)k * 4u) ^ cr));
            float4 tv = *(const float4*)(tr + k);
            acc += xv.x * tv.x + xv.y * tv.y + xv.z * tv.z + xv.w * tv.w;
        }
        dotv[j] = acc; rr2[j] = r; hh2[j] = h;
    }
    float srcv = 0.f;
    if (t < 8) {        // src term: row 0 (cr=0) vs T0 row t, vectorized __ldg
        const float* xr = (const float*)stageB;
        const float* t0 = gT0 + t * 128;
        #pragma unroll 4
        for (int k = 0; k < 128; k += 4) {
            float4 xv = *(const float4*)(xr + k);
            float4 tv = __ldg((const float4*)(t0 + k));
            srcv += xv.x * tv.x + xv.y * tv.y + xv.z * tv.z + xv.w * tv.w;
        }
    }
    __syncthreads();    // stage fully read; A image visible
    if (t < 8) sS[t] = srcv;

    // ---- chunk 0 -> buf0 (stage dead) ----
    #pragma unroll
    for (int i = 0; i < 4; ++i) {
        int u = t + i * 256;
        cp_async16(sb + SM_B + u * 16, &gWimg[u * 16]);
    }
    cp_commit();

    // ---- hoist A fragments (chunk-invariant): 32 regs ----
    const int mblk = w >> 1, nhalf = w & 1;
    const int ja = lane >> 3, ra = lane & 7;
    const int ml  = (ja & 1) * 8 + ra, kha = ja >> 1;
    const uint32_t arow = (((uint32_t)ml * 32u + (uint32_t)kha * 16u) ^ ((ml & 4) ? 16u : 0u));
    const uint32_t aad0 = sb + SM_A + (uint32_t)mblk * 4096u + arow;
    uint32_t af[8][4];
    #pragma unroll
    for (int kblk = 0; kblk < 8; ++kblk)
        LDSM_X4(af[kblk], aad0 + (uint32_t)kblk * 512u);
    __syncthreads();    // sS visible

    // ---- logits -> attb ----
    #pragma unroll
    for (int j = 0; j < 2; ++j) {
        int n = rr2[j];
        float v = sS[hh2[j]] + dotv[j];
        v = (v >= 0.f) ? v : 0.2f * v;
        attb[hh2[j] * 64 + n] = v;
    }
    __syncthreads();

    // ---- softmax: warp w -> head w ----
    {
        int m0 = mask[b * 64 + lane];
        int m1 = mask[b * 64 + lane + 32];
        float v0 = attb[w * 64 + lane]      + (m0 == 0 ? -1e9f : 0.f);
        float v1 = attb[w * 64 + lane + 32] + (m1 == 0 ? -1e9f : 0.f);
        float mx = fmaxf(v0, v1);
        #pragma unroll
        for (int o = 16; o > 0; o >>= 1) mx = fmaxf(mx, __shfl_xor_sync(0xffffffffu, mx, o));
        float e0 = __expf(v0 - mx), e1 = __expf(v1 - mx);
        float sum = e0 + e1;
        #pragma unroll
        for (int o = 16; o > 0; o >>= 1) sum += __shfl_xor_sync(0xffffffffu, sum, o);
        float inv = 1.f / sum;
        attb[w * 64 + lane]      = e0 * inv;
        attb[w * 64 + lane + 32] = e1 * inv;
    }

    // ---- B addressing + epilogue lane mapping (permuted columns) ----
    const int nbo = (ja >> 1), khb = ja & 1;
    const uint32_t brow = (((uint32_t)ra * 32u + (uint32_t)khb * 16u) ^ ((ra & 4) ? 16u : 0u));
    const int er = lane >> 2, jc = lane & 3;
    const int ns0 = mblk * 16 + er;                 // ns1 = ns0 + 8
    float* ob0 = out + ((size_t)b * 64 + ns0) * 512 + nhalf * 32 + jc * 8;

    // ---- mainloop: 8 chunks (chunk == head), double-buffered B ----
    for (int c = 0; c < 8; ++c) {
        cp_wait<0>();          // chunk c arrived
        __syncthreads();       // visibility + prior-chunk consumers done
        if (c < 7) {
            uint32_t dst = sb + SM_B + (uint32_t)((c + 1) & 1) * 16384u;
            #pragma unroll
            for (int i = 0; i < 4; ++i) {
                int u = t + i * 256;
                cp_async16(dst + u * 16, &gWimg[(c + 1) * 16384 + u * 16]);
            }
            cp_commit();
        }

        const uint32_t bbase = sb + SM_B + (uint32_t)(c & 1) * 16384u;
        float acc[16];
        #pragma unroll
        for (int i = 0; i < 16; ++i) acc[i] = 0.f;

        // depth-1 pipelined B stream: flat iter i = kblk*2 + ng
        uint32_t bh[2][4];
        {
            uint32_t bad = bbase + (uint32_t)(nhalf * 4 + nbo) * 2048u + brow;
            LDSM_X4(bh[0], bad);
        }
        #pragma unroll
        for (int i = 0; i < 16; ++i) {
            const int cur = i & 1, nxt = cur ^ 1;
            if (i < 15) {
                int kn = i + 1;
                uint32_t bad = bbase
                    + (uint32_t)(nhalf * 4 + (kn & 1) * 2 + nbo) * 2048u
                    + (uint32_t)(kn >> 1) * 256u + brow;
                LDSM_X4(bh[nxt], bad);
            }
            const int kblk = i >> 1, go = (i & 1) * 8;
            mmaf16(acc + go + 0, af[kblk], bh[cur][0], bh[cur][1]);
            mmaf16(acc + go + 4, af[kblk], bh[cur][2], bh[cur][3]);
        }

        // ---- epilogue: permuted cols => 8 contiguous floats per thread per row ----
        float sc0 = attb[c * 64 + ns0];
        float sc1 = attb[c * 64 + ns0 + 8];
        float* o0 = ob0 + c * 64;
        float4 v00 = make_float4(fmaxf(acc[0]  * sc0, 0.f), fmaxf(acc[1]  * sc0, 0.f),
                                 fmaxf(acc[4]  * sc0, 0.f), fmaxf(acc[5]  * sc0, 0.f));
        float4 v01 = make_float4(fmaxf(acc[8]  * sc0, 0.f), fmaxf(acc[9]  * sc0, 0.f),
                                 fmaxf(acc[12] * sc0, 0.f), fmaxf(acc[13] * sc0, 0.f));
        float4 v10 = make_float4(fmaxf(acc[2]  * sc1, 0.f), fmaxf(acc[3]  * sc1, 0.f),
                                 fmaxf(acc[6]  * sc1, 0.f), fmaxf(acc[7]  * sc1, 0.f));
        float4 v11 = make_float4(fmaxf(acc[10] * sc1, 0.f), fmaxf(acc[11] * sc1, 0.f),
                                 fmaxf(acc[14] * sc1, 0.f), fmaxf(acc[15] * sc1, 0.f));
        *(float4*)(o0)            = v00;
        *(float4*)(o0 + 4)        = v01;
        *(float4*)(o0 + 4096)     = v10;   // row ns0+8
        *(float4*)(o0 + 4096 + 4) = v11;
    }
}

// ---------------- launch ----------------
extern "C" void kernel_launch(void* const* d_in, const int* in_sizes, int n_in,
                              void* d_out, int out_size)
{
    const float* x    = (const float*)d_in[0];
    const float* Wlin = (const float*)d_in[1];
    const float* Watt = (const float*)d_in[2];
    const int*   mk   = (const int*)d_in[3];
    float*       out  = (float*)d_out;

    k_prep<<<96, 256>>>(Wlin, Watt);

    cudaFuncSetAttribute(agg_main, cudaFuncAttributeMaxDynamicSharedMemorySize, SMEM_BYTES);
    agg_main<<<BATCH, 256, SMEM_BYTES>>>(x, mk, out);
}

// round 16
// speedup vs baseline: 1.1906x; 1.0366x over previous
#include <cuda_runtime.h>
#include <cuda_fp16.h>
#include <cstdint>

#define BATCH 4096

// ---------------- device-global staging (written by pre-kernel) ----------------
// gWimg: fp16 B ldmatrix image, [chunk 8][nblk 8][kblk 8][tile 256B]
//   tile = 8 n-slots x 16 k fp16, slot nr at ((nr*32 + kh*16) ^ ((nr&4)?16:0)) + (k&7)*2
//   N-permutation: chunk=n>>6, cc=n&63, nhalf=cc>>5, w32=cc&31,
//     j=w32>>3, g=(w32>>1)&3, r=w32&1 ; nblk = nhalf*4 + g ; slot = 2j + r
__device__ __align__(1024) unsigned char gWimg[131072];
// gTt[half][h][f] = sum_c Wlin[f][c] * Watt[(half*512 + c)*8 + h]   (transposed)
__device__ __align__(16) float gTt[2][8][128];

// ---------------- PTX helpers ----------------
__device__ __forceinline__ uint32_t smem_u32(const void* p) {
    uint32_t a;
    asm("{ .reg .u64 t; cvta.to.shared.u64 t, %1; cvt.u32.u64 %0, t; }" : "=r"(a) : "l"(p));
    return a;
}
__device__ __forceinline__ void cp_async16(uint32_t saddr, const void* g) {
    asm volatile("cp.async.cg.shared.global [%0], [%1], 16;" :: "r"(saddr), "l"(g));
}
__device__ __forceinline__ void cp_commit() { asm volatile("cp.async.commit_group;"); }
template<int N> __device__ __forceinline__ void cp_wait() {
    asm volatile("cp.async.wait_group %0;" :: "n"(N));
}

#define LDSM_X4(d, a)                                                             \
    asm volatile("ldmatrix.sync.aligned.m8n8.x4.shared.b16 {%0,%1,%2,%3}, [%4];"  \
        : "=r"((d)[0]), "=r"((d)[1]), "=r"((d)[2]), "=r"((d)[3]) : "r"(a))

__device__ __forceinline__ void mmaf16(float* c, const uint32_t* a,
                                       uint32_t b0, uint32_t b1) {
    asm volatile("mma.sync.aligned.m16n8k16.row.col.f32.f16.f16.f32 "
        "{%0,%1,%2,%3}, {%4,%5,%6,%7}, {%8,%9}, {%0,%1,%2,%3};"
        : "+f"(c[0]), "+f"(c[1]), "+f"(c[2]), "+f"(c[3])
        : "r"(a[0]), "r"(a[1]), "r"(a[2]), "r"(a[3]), "r"(b0), "r"(b1));
}

__device__ __forceinline__ uint32_t pkh2(float a, float b) {
    __half2 t = __floats2half2_rn(a, b);
    return *reinterpret_cast<uint32_t*>(&t);
}

// ---------------- fused pre-kernel ----------------
__global__ void k_prep(const float* __restrict__ Wlin, const float* __restrict__ Watt) {
    int blk = blockIdx.x;
    if (blk < 32) {
        int t = blk * 256 + threadIdx.x;      // 0..8191
        int n = t & 511, ko = t >> 9;          // ko: 16 k-octs
        float v[8];
        #pragma unroll
        for (int j = 0; j < 8; ++j)
            v[j] = Wlin[(size_t)(ko * 8 + j) * 512 + n];
        int chunk = n >> 6, cc = n & 63, nhalf = cc >> 5, w32 = cc & 31;
        int jj = w32 >> 3, g = (w32 >> 1) & 3, r = w32 & 1;
        int nblk = chunk * 8 + nhalf * 4 + g;
        int nr = jj * 2 + r;
        int kblk = ko >> 1, kh = ko & 1;
        uint32_t off = (uint32_t)nblk * 2048u + (uint32_t)kblk * 256u
                     + (((uint32_t)nr * 32u + (uint32_t)kh * 16u) ^ ((nr & 4) ? 16u : 0u));
        *(uint4*)(&gWimg[off]) = make_uint4(pkh2(v[0], v[1]), pkh2(v[2], v[3]),
                                            pkh2(v[4], v[5]), pkh2(v[6], v[7]));
    } else {
        int t = (blk - 32) * 256 + threadIdx.x;   // 0..16383
        int o = t >> 3, sub = t & 7;               // 2048 outputs, 8 threads each
        int half = o >> 10, f = (o >> 3) & 127, h = o & 7;
        const float* wl = Wlin + (size_t)f * 512;
        const float* wa = Watt + (size_t)half * 512 * 8 + h;
        float acc = 0.f;
        int c0 = sub * 64;
        #pragma unroll 8
        for (int c = c0; c < c0 + 64; ++c)
            acc += wl[c] * wa[(size_t)c * 8];
        #pragma unroll
        for (int off = 4; off > 0; off >>= 1)
            acc += __shfl_xor_sync(0xffffffffu, acc, off);
        if (sub == 0) gTt[half][h][f] = acc;       // transposed store
    }
}

// ---------------- main kernel: 256 threads, 1 batch, 4 CTAs/SM ----------------
// Warp tiling: mblk = w>>1 (m=16), nhalf = w&1 (n=32)
// SMEM (bytes): A image [mblk4][kblk8][512B] @0 (16KB)
//               B double buffer 2 x 16KB @16384 (x stage, (row&7)*16 XOR, aliased)
//               T1t [8][132] fp32 @49152 ; SS[8] @53376 ; ATT[8][64] @53408
//               total 55456 -> 4 CTAs/SM
#define SM_A   0
#define SM_B   16384
#define SM_T1  49152
#define SM_SS  53376
#define SM_ATT 53408
#define SMEM_BYTES 55456

__global__ void __launch_bounds__(256, 4)
agg_main(const float* __restrict__ x, const int* __restrict__ mask,
         float* __restrict__ out)
{
    extern __shared__ unsigned char sm[];
    const int t = threadIdx.x, w = t >> 5, lane = t & 31;
    const int b = blockIdx.x;
    const uint32_t sb = smem_u32(sm);
    const unsigned char* stageB = sm + SM_B;       // swizzled x stage (aliased on B)
    float* attb  = (float*)(sm + SM_ATT);
    float* sS    = (float*)(sm + SM_SS);
    const float* sT1t = (float*)(sm + SM_T1);      // [8][132]
    const float* gT0  = &gTt[0][0][0];

    // ---- G0: x (32KB, (row&7)*16-swizzled) + T1t (rows padded to 132 floats) ----
    const float* xp = x + (size_t)b * 8192;
    #pragma unroll
    for (int i = 0; i < 8; ++i) {
        int idx = t + i * 256;                     // 16B chunk id, 0..2047
        int row = idx >> 5, cin = idx & 31;
        uint32_t dst = sb + SM_B + (uint32_t)row * 512u
                     + (((uint32_t)cin * 16u) ^ ((uint32_t)(row & 7) * 16u));
        cp_async16(dst, (const char*)xp + idx * 16);
    }
    {
        int h = t >> 5, c16 = t & 31;
        cp_async16(sb + SM_T1 + (uint32_t)h * 528u + (uint32_t)c16 * 16u,
                   (const char*)&gTt[1][0][0] + t * 16);
    }
    cp_commit();
    cp_wait<0>();
    __syncthreads();

    // ---- convert x -> fp16 A tile image ----
    // mapping: m = idx&63 (32 distinct rows per warp), k0 = (idx>>6)*8
    // => stage reads: 8 distinct 16B slots per quarter-warp (conflict-free)
    // => A writes: distinct (rr, mblk) per quarter-warp (conflict-free)
    #pragma unroll
    for (int i = 0; i < 4; ++i) {
        int idx = t + i * 256;
        int m = idx & 63, k0 = (idx >> 6) * 8;
        const unsigned char* rowp = stageB + m * 512;
        uint32_t cr = (uint32_t)(m & 7) * 16u;
        float4 v0 = *(const float4*)(rowp + (((uint32_t)k0 * 4u) ^ cr));
        float4 v1 = *(const float4*)(rowp + (((uint32_t)k0 * 4u + 16u) ^ cr));
        int mblk = m >> 4, rr = m & 15, kblk = k0 >> 4, kh = (k0 >> 3) & 1;
        uint32_t off = (uint32_t)mblk * 4096u + (uint32_t)kblk * 512u
                     + (((uint32_t)rr * 32u + (uint32_t)kh * 16u) ^ ((rr & 4) ? 16u : 0u));
        *(uint4*)(sm + SM_A + off) = make_uint4(pkh2(v0.x, v0.y), pkh2(v0.z, v0.w),
                                                pkh2(v1.x, v1.y), pkh2(v1.z, v1.w));
    }

    // ---- attention logits: 512 (r,h) tasks; x broadcast, T1t vectorized ----
    float dotv[2]; int rr2[2], hh2[2];
    #pragma unroll
    for (int j = 0; j < 2; ++j) {
        int idx2 = t + j * 256;
        int r = idx2 >> 3, h = idx2 & 7;
        const unsigned char* xrb = stageB + r * 512;
        uint32_t cr = (uint32_t)(r & 7) * 16u;
        const float* tr = sT1t + h * 132;
        float acc = 0.f;
        #pragma unroll 4
        for (int k = 0; k < 128; k += 4) {
            float4 xv = *(const float4*)(xrb + (((uint32_t)k * 4u) ^ cr));
            float4 tv = *(const float4*)(tr + k);
            acc += xv.x * tv.x + xv.y * tv.y + xv.z * tv.z + xv.w * tv.w;
        }
        dotv[j] = acc; rr2[j] = r; hh2[j] = h;
    }
    float srcv = 0.f;
    if (t < 8) {        // src term: row 0 (cr=0) vs T0 row t, vectorized __ldg
        const float* xr = (const float*)stageB;
        const float* t0 = gT0 + t * 128;
        #pragma unroll 4
        for (int k = 0; k < 128; k += 4) {
            float4 xv = *(const float4*)(xr + k);
            float4 tv = __ldg((const float4*)(t0 + k));
            srcv += xv.x * tv.x + xv.y * tv.y + xv.z * tv.z + xv.w * tv.w;
        }
    }
    __syncthreads();    // stage fully read; A image visible
    if (t < 8) sS[t] = srcv;

    // ---- chunk 0 -> buf0 (stage dead) ----
    #pragma unroll
    for (int i = 0; i < 4; ++i) {
        int u = t + i * 256;
        cp_async16(sb + SM_B + u * 16, &gWimg[u * 16]);
    }
    cp_commit();

    // ---- hoist A fragments (chunk-invariant): 32 regs ----
    const int mblk = w >> 1, nhalf = w & 1;
    const int ja = lane >> 3, ra = lane & 7;
    const int ml  = (ja & 1) * 8 + ra, kha = ja >> 1;
    const uint32_t arow = (((uint32_t)ml * 32u + (uint32_t)kha * 16u) ^ ((ml & 4) ? 16u : 0u));
    const uint32_t aad0 = sb + SM_A + (uint32_t)mblk * 4096u + arow;
    uint32_t af[8][4];
    #pragma unroll
    for (int kblk = 0; kblk < 8; ++kblk)
        LDSM_X4(af[kblk], aad0 + (uint32_t)kblk * 512u);
    __syncthreads();    // sS visible

    // ---- logits -> attb ----
    #pragma unroll
    for (int j = 0; j < 2; ++j) {
        int n = rr2[j];
        float v = sS[hh2[j]] + dotv[j];
        v = (v >= 0.f) ? v : 0.2f * v;
        attb[hh2[j] * 64 + n] = v;
    }
    __syncthreads();

    // ---- softmax: warp w -> head w ----
    {
        int m0 = mask[b * 64 + lane];
        int m1 = mask[b * 64 + lane + 32];
        float v0 = attb[w * 64 + lane]      + (m0 == 0 ? -1e9f : 0.f);
        float v1 = attb[w * 64 + lane + 32] + (m1 == 0 ? -1e9f : 0.f);
        float mx = fmaxf(v0, v1);
        #pragma unroll
        for (int o = 16; o > 0; o >>= 1) mx = fmaxf(mx, __shfl_xor_sync(0xffffffffu, mx, o));
        float e0 = __expf(v0 - mx), e1 = __expf(v1 - mx);
        float sum = e0 + e1;
        #pragma unroll
        for (int o = 16; o > 0; o >>= 1) sum += __shfl_xor_sync(0xffffffffu, sum, o);
        float inv = 1.f / sum;
        attb[w * 64 + lane]      = e0 * inv;
        attb[w * 64 + lane + 32] = e1 * inv;
    }

    // ---- B addressing + epilogue lane mapping (permuted columns) ----
    const int nbo = (ja >> 1), khb = ja & 1;
    const uint32_t brow = (((uint32_t)ra * 32u + (uint32_t)khb * 16u) ^ ((ra & 4) ? 16u : 0u));
    const int er = lane >> 2, jc = lane & 3;
    const int ns0 = mblk * 16 + er;                 // ns1 = ns0 + 8
    float* ob0 = out + ((size_t)b * 64 + ns0) * 512 + nhalf * 32 + jc * 8;

    // ---- mainloop: 8 chunks (chunk == head), double-buffered B ----
    for (int c = 0; c < 8; ++c) {
        cp_wait<0>();          // chunk c arrived
        __syncthreads();       // visibility + prior-chunk consumers done
        if (c < 7) {
            uint32_t dst = sb + SM_B + (uint32_t)((c + 1) & 1) * 16384u;
            #pragma unroll
            for (int i = 0; i < 4; ++i) {
                int u = t + i * 256;
                cp_async16(dst + u * 16, &gWimg[(c + 1) * 16384 + u * 16]);
            }
            cp_commit();
        }

        const uint32_t bbase = sb + SM_B + (uint32_t)(c & 1) * 16384u;
        float acc[16];
        #pragma unroll
        for (int i = 0; i < 16; ++i) acc[i] = 0.f;

        // depth-1 pipelined B stream: flat iter i = kblk*2 + ng
        uint32_t bh[2][4];
        {
            uint32_t bad = bbase + (uint32_t)(nhalf * 4 + nbo) * 2048u + brow;
            LDSM_X4(bh[0], bad);
        }
        #pragma unroll
        for (int i = 0; i < 16; ++i) {
            const int cur = i & 1, nxt = cur ^ 1;
            if (i < 15) {
                int kn = i + 1;
                uint32_t bad = bbase
                    + (uint32_t)(nhalf * 4 + (kn & 1) * 2 + nbo) * 2048u
                    + (uint32_t)(kn >> 1) * 256u + brow;
                LDSM_X4(bh[nxt], bad);
            }
            const int kblk = i >> 1, go = (i & 1) * 8;
            mmaf16(acc + go + 0, af[kblk], bh[cur][0], bh[cur][1]);
            mmaf16(acc + go + 4, af[kblk], bh[cur][2], bh[cur][3]);
        }

        // ---- epilogue: permuted cols => 8 contiguous floats per thread per row ----
        float sc0 = attb[c * 64 + ns0];
        float sc1 = attb[c * 64 + ns0 + 8];
        float* o0 = ob0 + c * 64;
        float4 v00 = make_float4(fmaxf(acc[0]  * sc0, 0.f), fmaxf(acc[1]  * sc0, 0.f),
                                 fmaxf(acc[4]  * sc0, 0.f), fmaxf(acc[5]  * sc0, 0.f));
        float4 v01 = make_float4(fmaxf(acc[8]  * sc0, 0.f), fmaxf(acc[9]  * sc0, 0.f),
                                 fmaxf(acc[12] * sc0, 0.f), fmaxf(acc[13] * sc0, 0.f));
        float4 v10 = make_float4(fmaxf(acc[2]  * sc1, 0.f), fmaxf(acc[3]  * sc1, 0.f),
                                 fmaxf(acc[6]  * sc1, 0.f), fmaxf(acc[7]  * sc1, 0.f));
        float4 v11 = make_float4(fmaxf(acc[10] * sc1, 0.f), fmaxf(acc[11] * sc1, 0.f),
                                 fmaxf(acc[14] * sc1, 0.f), fmaxf(acc[15] * sc1, 0.f));
        *(float4*)(o0)            = v00;
        *(float4*)(o0 + 4)        = v01;
        *(float4*)(o0 + 4096)     = v10;   // row ns0+8
        *(float4*)(o0 + 4096 + 4) = v11;
    }
}

// ---------------- launch ----------------
extern "C" void kernel_launch(void* const* d_in, const int* in_sizes, int n_in,
                              void* d_out, int out_size)
{
    const float* x    = (const float*)d_in[0];
    const float* Wlin = (const float*)d_in[1];
    const float* Watt = (const float*)d_in[2];
    const int*   mk   = (const int*)d_in[3];
    float*       out  = (float*)d_out;

    k_prep<<<96, 256>>>(Wlin, Watt);

    cudaFuncSetAttribute(agg_main, cudaFuncAttributeMaxDynamicSharedMemorySize, SMEM_BYTES);
    agg_main<<<BATCH, 256, SMEM_BYTES>>>(x, mk, out);
}

// round 17
// speedup vs baseline: 1.1987x; 1.0068x over previous
#include <cuda_runtime.h>
#include <cuda_fp16.h>
#include <cstdint>

#define BATCH 4096

// ---------------- device-global staging (written by pre-kernel) ----------------
// gWimg: fp16 B ldmatrix image, [chunk 8][nblk 8][kblk 8][tile 256B]
//   tile = 8 n-slots x 16 k fp16, slot nr at ((nr*32 + kh*16) ^ ((nr&4)?16:0)) + (k&7)*2
//   N-permutation: chunk=n>>6, cc=n&63, nhalf=cc>>5, w32=cc&31,
//     j=w32>>3, g=(w32>>1)&3, r=w32&1 ; nblk = nhalf*4 + g ; slot = 2j + r
__device__ __align__(1024) unsigned char gWimg[131072];
// gTt[half][h][f] = sum_c Wlin[f][c] * Watt[(half*512 + c)*8 + h]   (transposed)
__device__ __align__(16) float gTt[2][8][128];

// ---------------- PTX helpers ----------------
__device__ __forceinline__ uint32_t smem_u32(const void* p) {
    uint32_t a;
    asm("{ .reg .u64 t; cvta.to.shared.u64 t, %1; cvt.u32.u64 %0, t; }" : "=r"(a) : "l"(p));
    return a;
}
__device__ __forceinline__ void cp_async16(uint32_t saddr, const void* g) {
    asm volatile("cp.async.cg.shared.global [%0], [%1], 16;" :: "r"(saddr), "l"(g));
}
__device__ __forceinline__ void cp_commit() { asm volatile("cp.async.commit_group;"); }
template<int N> __device__ __forceinline__ void cp_wait() {
    asm volatile("cp.async.wait_group %0;" :: "n"(N));
}

// ---- bulk copy (TMA path, sm_90 PTX) + mbarrier ----
#define MBAR_INIT(a, c) \
    asm volatile("mbarrier.init.shared.b64 [%0], %1;" :: "r"(a), "r"(c) : "memory")
#define MBAR_EXPECT_TX(a, n) \
    asm volatile("mbarrier.arrive.expect_tx.shared.b64 _, [%0], %1;" :: "r"(a), "r"(n) : "memory")
#define MBAR_WAIT(mbar, parity) do {                                              \
    uint32_t _m = (mbar); uint32_t _p = (parity); uint32_t _done;                 \
    asm volatile("{\n\t.reg .pred p;\n\t"                                         \
        "mbarrier.try_wait.parity.acquire.cta.shared::cta.b64 p, [%1], %2;\n\t"   \
        "selp.b32 %0, 1, 0, p;\n\t}"                                              \
        : "=r"(_done) : "r"(_m), "r"(_p) : "memory");                             \
    if (!_done) {                                                                 \
        asm volatile("{\n\t.reg .pred P1;\n\t"                                    \
            "WL_%=:\n\t"                                                          \
            "mbarrier.try_wait.parity.acquire.cta.shared::cta.b64 P1, [%0], %1, 0x989680;\n\t" \
            "@P1 bra.uni WD_%=;\n\t"                                              \
            "bra.uni WL_%=;\n\t"                                                  \
            "WD_%=:\n\t}"                                                         \
            :: "r"(_m), "r"(_p) : "memory");                                      \
    }                                                                             \
} while (0)
__device__ __forceinline__ void bulk_g2s(uint32_t dst, const void* src,
                                         uint32_t bytes, uint32_t mbar) {
    asm volatile(
        "cp.async.bulk.shared::cta.global.mbarrier::complete_tx::bytes [%0], [%1], %2, [%3];"
        :: "r"(dst), "l"(src), "r"(bytes), "r"(mbar) : "memory");
}

#define LDSM_X4(d, a)                                                             \
    asm volatile("ldmatrix.sync.aligned.m8n8.x4.shared.b16 {%0,%1,%2,%3}, [%4];"  \
        : "=r"((d)[0]), "=r"((d)[1]), "=r"((d)[2]), "=r"((d)[3]) : "r"(a))

__device__ __forceinline__ void mmaf16(float* c, const uint32_t* a,
                                       uint32_t b0, uint32_t b1) {
    asm volatile("mma.sync.aligned.m16n8k16.row.col.f32.f16.f16.f32 "
        "{%0,%1,%2,%3}, {%4,%5,%6,%7}, {%8,%9}, {%0,%1,%2,%3};"
        : "+f"(c[0]), "+f"(c[1]), "+f"(c[2]), "+f"(c[3])
        : "r"(a[0]), "r"(a[1]), "r"(a[2]), "r"(a[3]), "r"(b0), "r"(b1));
}

__device__ __forceinline__ uint32_t pkh2(float a, float b) {
    __half2 t = __floats2half2_rn(a, b);
    return *reinterpret_cast<uint32_t*>(&t);
}

// ---------------- fused pre-kernel (unchanged) ----------------
__global__ void k_prep(const float* __restrict__ Wlin, const float* __restrict__ Watt) {
    int blk = blockIdx.x;
    if (blk < 32) {
        int t = blk * 256 + threadIdx.x;      // 0..8191
        int n = t & 511, ko = t >> 9;          // ko: 16 k-octs
        float v[8];
        #pragma unroll
        for (int j = 0; j < 8; ++j)
            v[j] = Wlin[(size_t)(ko * 8 + j) * 512 + n];
        int chunk = n >> 6, cc = n & 63, nhalf = cc >> 5, w32 = cc & 31;
        int jj = w32 >> 3, g = (w32 >> 1) & 3, r = w32 & 1;
        int nblk = chunk * 8 + nhalf * 4 + g;
        int nr = jj * 2 + r;
        int kblk = ko >> 1, kh = ko & 1;
        uint32_t off = (uint32_t)nblk * 2048u + (uint32_t)kblk * 256u
                     + (((uint32_t)nr * 32u + (uint32_t)kh * 16u) ^ ((nr & 4) ? 16u : 0u));
        *(uint4*)(&gWimg[off]) = make_uint4(pkh2(v[0], v[1]), pkh2(v[2], v[3]),
                                            pkh2(v[4], v[5]), pkh2(v[6], v[7]));
    } else {
        int t = (blk - 32) * 256 + threadIdx.x;   // 0..16383
        int o = t >> 3, sub = t & 7;               // 2048 outputs, 8 threads each
        int half = o >> 10, f = (o >> 3) & 127, h = o & 7;
        const float* wl = Wlin + (size_t)f * 512;
        const float* wa = Watt + (size_t)half * 512 * 8 + h;
        float acc = 0.f;
        int c0 = sub * 64;
        #pragma unroll 8
        for (int c = c0; c < c0 + 64; ++c)
            acc += wl[c] * wa[(size_t)c * 8];
        #pragma unroll
        for (int off = 4; off > 0; off >>= 1)
            acc += __shfl_xor_sync(0xffffffffu, acc, off);
        if (sub == 0) gTt[half][h][f] = acc;       // transposed store
    }
}

// ---------------- main kernel: 256 threads, 1 batch, 4 CTAs/SM ----------------
// Warp tiling: mblk = w>>1 (m=16), nhalf = w&1 (n=32)
// SMEM (bytes): A image @0 (16KB) ; B double buffer 2x16KB @16384 (x stage aliased)
//               T1t [8][132] @49152 ; SS[8] @53376 ; ATT[8][64] @53408
//               mbar[2] @55456 ; total 55472
#define SM_A    0
#define SM_B    16384
#define SM_T1   49152
#define SM_SS   53376
#define SM_ATT  53408
#define SM_MBAR 55456
#define SMEM_BYTES 55472

__global__ void __launch_bounds__(256, 4)
agg_main(const float* __restrict__ x, const int* __restrict__ mask,
         float* __restrict__ out)
{
    extern __shared__ unsigned char sm[];
    const int t = threadIdx.x, w = t >> 5, lane = t & 31;
    const int b = blockIdx.x;
    const uint32_t sb = smem_u32(sm);
    const unsigned char* stageB = sm + SM_B;       // swizzled x stage (aliased on B)
    float* attb  = (float*)(sm + SM_ATT);
    float* sS    = (float*)(sm + SM_SS);
    const float* sT1t = (float*)(sm + SM_T1);      // [8][132]
    const float* gT0  = &gTt[0][0][0];

    // ---- mbarrier init (count 1: single expect_tx arriver per phase) ----
    if (t == 0) {
        MBAR_INIT(sb + SM_MBAR, 1);
        MBAR_INIT(sb + SM_MBAR + 8, 1);
    }

    // ---- G0: x (32KB, (row&7)*16-swizzled) + T1t (rows padded to 132 floats) ----
    const float* xp = x + (size_t)b * 8192;
    #pragma unroll
    for (int i = 0; i < 8; ++i) {
        int idx = t + i * 256;                     // 16B chunk id, 0..2047
        int row = idx >> 5, cin = idx & 31;
        uint32_t dst = sb + SM_B + (uint32_t)row * 512u
                     + (((uint32_t)cin * 16u) ^ ((uint32_t)(row & 7) * 16u));
        cp_async16(dst, (const char*)xp + idx * 16);
    }
    {
        int h = t >> 5, c16 = t & 31;
        cp_async16(sb + SM_T1 + (uint32_t)h * 528u + (uint32_t)c16 * 16u,
                   (const char*)&gTt[1][0][0] + t * 16);
    }
    cp_commit();
    cp_wait<0>();
    __syncthreads();    // x staged; mbarriers initialized & visible

    // ---- convert x -> fp16 A tile image (conflict-free mapping) ----
    #pragma unroll
    for (int i = 0; i < 4; ++i) {
        int idx = t + i * 256;
        int m = idx & 63, k0 = (idx >> 6) * 8;
        const unsigned char* rowp = stageB + m * 512;
        uint32_t cr = (uint32_t)(m & 7) * 16u;
        float4 v0 = *(const float4*)(rowp + (((uint32_t)k0 * 4u) ^ cr));
        float4 v1 = *(const float4*)(rowp + (((uint32_t)k0 * 4u + 16u) ^ cr));
        int mblk = m >> 4, rr = m & 15, kblk = k0 >> 4, kh = (k0 >> 3) & 1;
        uint32_t off = (uint32_t)mblk * 4096u + (uint32_t)kblk * 512u
                     + (((uint32_t)rr * 32u + (uint32_t)kh * 16u) ^ ((rr & 4) ? 16u : 0u));
        *(uint4*)(sm + SM_A + off) = make_uint4(pkh2(v0.x, v0.y), pkh2(v0.z, v0.w),
                                                pkh2(v1.x, v1.y), pkh2(v1.z, v1.w));
    }

    // ---- attention logits: 512 (r,h) tasks; x broadcast, T1t vectorized ----
    float dotv[2]; int rr2[2], hh2[2];
    #pragma unroll
    for (int j = 0; j < 2; ++j) {
        int idx2 = t + j * 256;
        int r = idx2 >> 3, h = idx2 & 7;
        const unsigned char* xrb = stageB + r * 512;
        uint32_t cr = (uint32_t)(r & 7) * 16u;
        const float* tr = sT1t + h * 132;
        float acc = 0.f;
        #pragma unroll 4
        for (int k = 0; k < 128; k += 4) {
            float4 xv = *(const float4*)(xrb + (((uint32_t)k * 4u) ^ cr));
            float4 tv = *(const float4*)(tr + k);
            acc += xv.x * tv.x + xv.y * tv.y + xv.z * tv.z + xv.w * tv.w;
        }
        dotv[j] = acc; rr2[j] = r; hh2[j] = h;
    }
    float srcv = 0.f;
    if (t < 8) {        // src term: row 0 (cr=0) vs T0 row t, vectorized __ldg
        const float* xr = (const float*)stageB;
        const float* t0 = gT0 + t * 128;
        #pragma unroll 4
        for (int k = 0; k < 128; k += 4) {
            float4 xv = *(const float4*)(xr + k);
            float4 tv = __ldg((const float4*)(t0 + k));
            srcv += xv.x * tv.x + xv.y * tv.y + xv.z * tv.z + xv.w * tv.w;
        }
    }
    __syncthreads();    // stage fully read; A image visible
    if (t < 8) sS[t] = srcv;

    // ---- chunk 0 -> buf0 via bulk copy (stage dead) ----
    if (t == 0) {
        MBAR_EXPECT_TX(sb + SM_MBAR, 16384u);
        bulk_g2s(sb + SM_B, &gWimg[0], 16384u, sb + SM_MBAR);
    }

    // ---- hoist A fragments (chunk-invariant): 32 regs ----
    const int mblk = w >> 1, nhalf = w & 1;
    const int ja = lane >> 3, ra = lane & 7;
    const int ml  = (ja & 1) * 8 + ra, kha = ja >> 1;
    const uint32_t arow = (((uint32_t)ml * 32u + (uint32_t)kha * 16u) ^ ((ml & 4) ? 16u : 0u));
    const uint32_t aad0 = sb + SM_A + (uint32_t)mblk * 4096u + arow;
    uint32_t af[8][4];
    #pragma unroll
    for (int kblk = 0; kblk < 8; ++kblk)
        LDSM_X4(af[kblk], aad0 + (uint32_t)kblk * 512u);
    __syncthreads();    // sS visible

    // ---- logits -> attb ----
    #pragma unroll
    for (int j = 0; j < 2; ++j) {
        int n = rr2[j];
        float v = sS[hh2[j]] + dotv[j];
        v = (v >= 0.f) ? v : 0.2f * v;
        attb[hh2[j] * 64 + n] = v;
    }
    __syncthreads();

    // ---- softmax: warp w -> head w ----
    {
        int m0 = mask[b * 64 + lane];
        int m1 = mask[b * 64 + lane + 32];
        float v0 = attb[w * 64 + lane]      + (m0 == 0 ? -1e9f : 0.f);
        float v1 = attb[w * 64 + lane + 32] + (m1 == 0 ? -1e9f : 0.f);
        float mx = fmaxf(v0, v1);
        #pragma unroll
        for (int o = 16; o > 0; o >>= 1) mx = fmaxf(mx, __shfl_xor_sync(0xffffffffu, mx, o));
        float e0 = __expf(v0 - mx), e1 = __expf(v1 - mx);
        float sum = e0 + e1;
        #pragma unroll
        for (int o = 16; o > 0; o >>= 1) sum += __shfl_xor_sync(0xffffffffu, sum, o);
        float inv = 1.f / sum;
        attb[w * 64 + lane]      = e0 * inv;
        attb[w * 64 + lane + 32] = e1 * inv;
    }

    // ---- B addressing + epilogue lane mapping (permuted columns) ----
    const int nbo = (ja >> 1), khb = ja & 1;
    const uint32_t brow = (((uint32_t)ra * 32u + (uint32_t)khb * 16u) ^ ((ra & 4) ? 16u : 0u));
    const int er = lane >> 2, jc = lane & 3;
    const int ns0 = mblk * 16 + er;                 // ns1 = ns0 + 8
    float* ob0 = out + ((size_t)b * 64 + ns0) * 512 + nhalf * 32 + jc * 8;

    // ---- mainloop: 8 chunks (chunk == head), double-buffered B via bulk/TMA ----
    for (int c = 0; c < 8; ++c) {
        MBAR_WAIT(sb + SM_MBAR + (uint32_t)(c & 1) * 8u, (c >> 1) & 1);  // chunk c data
        __syncthreads();       // all warps done with chunk c-1's buffer
        if (c < 7 && t == 0) {
            uint32_t mb  = sb + SM_MBAR + (uint32_t)((c + 1) & 1) * 8u;
            uint32_t dst = sb + SM_B + (uint32_t)((c + 1) & 1) * 16384u;
            MBAR_EXPECT_TX(mb, 16384u);
            bulk_g2s(dst, &gWimg[(c + 1) * 16384], 16384u, mb);
        }

        const uint32_t bbase = sb + SM_B + (uint32_t)(c & 1) * 16384u;
        float acc[16];
        #pragma unroll
        for (int i = 0; i < 16; ++i) acc[i] = 0.f;

        // depth-1 pipelined B stream: flat iter i = kblk*2 + ng
        uint32_t bh[2][4];
        {
            uint32_t bad = bbase + (uint32_t)(nhalf * 4 + nbo) * 2048u + brow;
            LDSM_X4(bh[0], bad);
        }
        #pragma unroll
        for (int i = 0; i < 16; ++i) {
            const int cur = i & 1, nxt = cur ^ 1;
            if (i < 15) {
                int kn = i + 1;
                uint32_t bad = bbase
                    + (uint32_t)(nhalf * 4 + (kn & 1) * 2 + nbo) * 2048u
                    + (uint32_t)(kn >> 1) * 256u + brow;
                LDSM_X4(bh[nxt], bad);
            }
            const int kblk = i >> 1, go = (i & 1) * 8;
            mmaf16(acc + go + 0, af[kblk], bh[cur][0], bh[cur][1]);
            mmaf16(acc + go + 4, af[kblk], bh[cur][2], bh[cur][3]);
        }

        // ---- epilogue: permuted cols => 8 contiguous floats per thread per row ----
        float sc0 = attb[c * 64 + ns0];
        float sc1 = attb[c * 64 + ns0 + 8];
        float* o0 = ob0 + c * 64;
        float4 v00 = make_float4(fmaxf(acc[0]  * sc0, 0.f), fmaxf(acc[1]  * sc0, 0.f),
                                 fmaxf(acc[4]  * sc0, 0.f), fmaxf(acc[5]  * sc0, 0.f));
        float4 v01 = make_float4(fmaxf(acc[8]  * sc0, 0.f), fmaxf(acc[9]  * sc0, 0.f),
                                 fmaxf(acc[12] * sc0, 0.f), fmaxf(acc[13] * sc0, 0.f));
        float4 v10 = make_float4(fmaxf(acc[2]  * sc1, 0.f), fmaxf(acc[3]  * sc1, 0.f),
                                 fmaxf(acc[6]  * sc1, 0.f), fmaxf(acc[7]  * sc1, 0.f));
        float4 v11 = make_float4(fmaxf(acc[10] * sc1, 0.f), fmaxf(acc[11] * sc1, 0.f),
                                 fmaxf(acc[14] * sc1, 0.f), fmaxf(acc[15] * sc1, 0.f));
        *(float4*)(o0)            = v00;
        *(float4*)(o0 + 4)        = v01;
        *(float4*)(o0 + 4096)     = v10;   // row ns0+8
        *(float4*)(o0 + 4096 + 4) = v11;
    }
}

// ---------------- launch ----------------
extern "C" void kernel_launch(void* const* d_in, const int* in_sizes, int n_in,
                              void* d_out, int out_size)
{
    const float* x    = (const float*)d_in[0];
    const float* Wlin = (const float*)d_in[1];
    const float* Watt = (const float*)d_in[2];
    const int*   mk   = (const int*)d_in[3];
    float*       out  = (float*)d_out;

    k_prep<<<96, 256>>>(Wlin, Watt);

    cudaFuncSetAttribute(agg_main, cudaFuncAttributeMaxDynamicSharedMemorySize, SMEM_BYTES);
    agg_main<<<BATCH, 256, SMEM_BYTES>>>(x, mk, out);
}